// round 1
// baseline (speedup 1.0000x reference)
#include <cuda_runtime.h>

// EfficientAttention fused kernel for B200 (sm_100a build target).
// One CTA per (n,i) row: B*H = 512 rows, W=160, C=64, M=10, WIDTH=5.
//
// Pipeline per row:
//   1) load L,R row -> smem transposed Qt[c][QROW] (odd stride 165: conflict-free
//      for conv (lanes vary j) AND gather (lanes vary k)); zero-padded 2 cols each
//      side for SAME conv padding.
//   2) conv 1x5 over 128 in-ch -> 10 logits, m packed as f32x2 pairs
//      (fma.rn.f32x2), thread = (j, c-quarter), partial logits reduced via smem.
//   3) softmax over m (160 threads), weights -> smem + both weight outputs.
//   4) shiftmap gather (circular roll) + BN + tanh, thread = (k, j-group of 16)
//      with sliding register windows so each smem value is read once per k-owner.

#define W_DIM 160
#define C_DIM 64
#define QROW  165          // [2 zero | 160 data | 3 zero], odd => conflict-free
#define KROW  52           // 50 K floats per c, padded to 16B multiple
#define NTHR  640
#define X_SIZE   5242880   // 4*128*160*64
#define W_OFF1   5242880
#define W_OFF2   6062080   // W_OFF1 + 4*128*160*10

__device__ __forceinline__ unsigned long long pack2(float lo, float hi) {
    unsigned long long r;
    asm("mov.b64 %0, {%1, %2};" : "=l"(r) : "f"(lo), "f"(hi));
    return r;
}
__device__ __forceinline__ void unpack2(unsigned long long v, float& lo, float& hi) {
    asm("mov.b64 {%0, %1}, %2;" : "=f"(lo), "=f"(hi) : "l"(v));
}
__device__ __forceinline__ void fma2(unsigned long long& d, unsigned long long a,
                                     unsigned long long b) {
    asm("fma.rn.f32x2 %0, %1, %2, %3;" : "=l"(d) : "l"(a), "l"(b), "l"(d));
}

__global__ void __launch_bounds__(NTHR, 1)
ea_kernel(const float* __restrict__ gL, const float* __restrict__ gR,
          const float* __restrict__ gK, const float* __restrict__ gBias,
          const float* __restrict__ gGamma, const float* __restrict__ gBeta,
          const float* __restrict__ gMean, const float* __restrict__ gVar,
          float* __restrict__ out)
{
    extern __shared__ float sm[];
    float* Qt = sm;                        // 128*165 floats (L ch 0..63, R ch 64..127)
    float* Kc = Qt + 128 * QROW;           // 128*52:  Kc[c][w*10+m]
    float* W4 = Kc + 128 * KROW;           // 4*160*11: per-quarter logit partials
    float* WS = W4 + 4 * 160 * 11;         // 160*12:  softmaxed weights (pair-aligned)

    const int t   = threadIdx.x;
    const int row = blockIdx.x;            // n*H + i
    const float* Lrow = gL + (size_t)row * (W_DIM * C_DIM);
    const float* Rrow = gR + (size_t)row * (W_DIM * C_DIM);

    // ---- zero the SAME-conv padding columns (128 ch x 5 pad cols = 640) ----
    {
        int c = t / 5, pc = t % 5;
        int col = (pc < 2) ? pc : (pc + 160);
        Qt[c * QROW + col] = 0.f;
    }

    // ---- load L,R rows (coalesced float4) -> transposed smem ----
    #pragma unroll
    for (int kk = 0; kk < 4; kk++) {
        int i4 = t + kk * NTHR;                    // 0..2559, = j*16 + cquad
        int j = i4 >> 4, c = (i4 & 15) << 2;
        float4 v = reinterpret_cast<const float4*>(Lrow)[i4];
        Qt[(c + 0) * QROW + 2 + j] = v.x;
        Qt[(c + 1) * QROW + 2 + j] = v.y;
        Qt[(c + 2) * QROW + 2 + j] = v.z;
        Qt[(c + 3) * QROW + 2 + j] = v.w;
        float4 u = reinterpret_cast<const float4*>(Rrow)[i4];
        Qt[(c + 64) * QROW + 2 + j] = u.x;
        Qt[(c + 65) * QROW + 2 + j] = u.y;
        Qt[(c + 66) * QROW + 2 + j] = u.z;
        Qt[(c + 67) * QROW + 2 + j] = u.w;
    }

    // ---- load conv kernel, HWIO (w,c,m) -> Kc[c][w*10+m] ----
    #pragma unroll
    for (int kk = 0; kk < 10; kk++) {
        int g = t + kk * NTHR;                     // 0..6399
        int m = g % 10;
        int wc = g / 10;
        int c = wc & 127;
        int w = g / 1280;
        Kc[c * KROW + w * 10 + m] = gK[g];
    }
    __syncthreads();

    // ---- conv: thread = (j, c-quarter), 32 channels each ----
    {
        const int j  = t % 160;
        const int cq = t / 160;
        unsigned long long acc[5];                 // m-pairs (0,1)(2,3)(4,5)(6,7)(8,9)
        #pragma unroll
        for (int p = 0; p < 5; p++) acc[p] = 0ull;

        const float* qbase = Qt + (cq * 32) * QROW + j;   // cols j..j+4 = query j-2..j+2
        const float* kbase = Kc + (cq * 32) * KROW;

        #pragma unroll 2
        for (int ci = 0; ci < 32; ci++) {
            const float* q = qbase + ci * QROW;
            unsigned long long qs0 = pack2(q[0], q[0]);
            unsigned long long qs1 = pack2(q[1], q[1]);
            unsigned long long qs2 = pack2(q[2], q[2]);
            unsigned long long qs3 = pack2(q[3], q[3]);
            unsigned long long qs4 = pack2(q[4], q[4]);
            unsigned long long qs[5] = {qs0, qs1, qs2, qs3, qs4};

            const float* krow = kbase + ci * KROW;
            const ulonglong2* kp = reinterpret_cast<const ulonglong2*>(krow);
            #pragma unroll
            for (int i = 0; i < 12; i++) {
                ulonglong2 kv = kp[i];             // LDS.128 broadcast
                const int pi0 = 2 * i, pi1 = 2 * i + 1;
                fma2(acc[pi0 % 5], qs[pi0 / 5], kv.x);
                fma2(acc[pi1 % 5], qs[pi1 / 5], kv.y);
            }
            fma2(acc[4], qs[4],
                 reinterpret_cast<const unsigned long long*>(krow)[24]);
        }

        float* wd = W4 + (cq * 160 + j) * 11;      // odd stride => conflict-free
        #pragma unroll
        for (int p = 0; p < 5; p++) {
            float lo, hi;
            unpack2(acc[p], lo, hi);
            wd[2 * p]     = lo;
            wd[2 * p + 1] = hi;
        }
    }
    __syncthreads();

    // ---- logit reduction + softmax + weight outputs (threads 0..159) ----
    if (t < 160) {
        float v[10];
        #pragma unroll
        for (int m = 0; m < 10; m++) {
            v[m] = gBias[m]
                 + W4[(0 * 160 + t) * 11 + m]
                 + W4[(1 * 160 + t) * 11 + m]
                 + W4[(2 * 160 + t) * 11 + m]
                 + W4[(3 * 160 + t) * 11 + m];
        }
        float mx = v[0];
        #pragma unroll
        for (int m = 1; m < 10; m++) mx = fmaxf(mx, v[m]);
        float s = 0.f;
        #pragma unroll
        for (int m = 0; m < 10; m++) { float e = __expf(v[m] - mx); v[m] = e; s += e; }
        float inv = 1.f / s;
        float* wr = WS + t * 12;
        size_t wo = (size_t)row * 1600 + (size_t)t * 10;
        #pragma unroll
        for (int m = 0; m < 10; m++) {
            float wv = v[m] * inv;
            wr[m] = wv;
            out[W_OFF1 + wo + m] = wv;
            out[W_OFF2 + wo + m] = wv;
        }
    }
    __syncthreads();

    // ---- shiftmap gather + BN + tanh: thread = (k, group of 16 j) ----
    {
        const int k  = t & 63;
        const int g  = t >> 6;                     // 0..9
        const int j0 = g * 16;

        float sc = gGamma[k] / sqrtf(gVar[k] + 1e-3f);
        float sh = gBeta[k] - gMean[k] * sc;

        const float* Lc = Qt + k * QROW + 2;       // data columns
        const float* Rc = Qt + (64 + k) * QROW + 2;

        // sliding windows: lw[s] = L[(j - s) mod 160], rw[s] = R[(j + s) mod 160]
        float lw[5], rw[5];
        #pragma unroll
        for (int s = 0; s < 5; s++) {
            int li = j0 - s; if (li < 0) li += 160;
            lw[s] = Lc[li];
            rw[s] = Rc[j0 + s];                    // j0+s <= 148, no wrap at init
        }

        float* xout = out + (size_t)(row * 160 + j0) * 64 + k;
        #pragma unroll
        for (int jj = 0; jj < 16; jj++) {
            int j = j0 + jj;
            const unsigned long long* wp =
                reinterpret_cast<const unsigned long long*>(WS + j * 12);
            unsigned long long a = 0ull;
            #pragma unroll
            for (int s = 0; s < 5; s++)            // {w2s,w2s+1} x {L shift, R shift}
                fma2(a, wp[s], pack2(lw[s], rw[s]));
            float lo, hi;
            unpack2(a, lo, hi);
            float x = (lo + hi) * sc + sh;         // inference BN
            float e = __expf(2.f * x);             // tanh = 1 - 2/(e^{2x}+1)
            x = 1.f - 2.f / (e + 1.f);
            xout[(size_t)jj * 64] = x;

            int ln = j + 1; if (ln >= 160) ln -= 160;
            int rn = j + 5; if (rn >= 160) rn -= 160;
            lw[4] = lw[3]; lw[3] = lw[2]; lw[2] = lw[1]; lw[1] = lw[0];
            lw[0] = Lc[ln];
            rw[0] = rw[1]; rw[1] = rw[2]; rw[2] = rw[3]; rw[3] = rw[4];
            rw[4] = Rc[rn];
        }
    }
}

extern "C" void kernel_launch(void* const* d_in, const int* in_sizes, int n_in,
                              void* d_out, int out_size)
{
    const float* L     = (const float*)d_in[0];
    const float* R     = (const float*)d_in[1];
    const float* K     = (const float*)d_in[2];
    const float* bias  = (const float*)d_in[3];
    const float* gamma = (const float*)d_in[4];
    const float* beta  = (const float*)d_in[5];
    const float* mean  = (const float*)d_in[6];
    const float* var   = (const float*)d_in[7];
    float* out = (float*)d_out;

    const int smem = (128 * QROW + 128 * KROW + 4 * 160 * 11 + 160 * 12) * 4; // 146944 B
    cudaFuncSetAttribute(ea_kernel, cudaFuncAttributeMaxDynamicSharedMemorySize, smem);
    ea_kernel<<<512, NTHR, smem>>>(L, R, K, bias, gamma, beta, mean, var, out);
}

// round 3
// speedup vs baseline: 1.2937x; 1.2937x over previous
#include <cuda_runtime.h>

// EfficientAttention fused kernel (sm_100a). One CTA per (n,i) row.
// R2/R3: conv computes a PAIR of adjacent j per thread (T=2), sharing the
// K vector loads between both outputs and overlapping the q windows
// (6 scalar loads instead of 10). Conv LDS per thread: 576 -> 304.
// (R3 is a resubmit of R2 after an infra-side container failure.)

#define W_DIM 160
#define C_DIM 64
#define QROW  165          // [2 zero | 160 data | 3 zero], odd => conflict-free
#define KROW  52           // 50 K floats per c, padded to 16B multiple
#define NTHR  640
#define W_OFF1   5242880   // 4*128*160*64
#define W_OFF2   6062080   // W_OFF1 + 4*128*160*10

__device__ __forceinline__ unsigned long long pack2(float lo, float hi) {
    unsigned long long r;
    asm("mov.b64 %0, {%1, %2};" : "=l"(r) : "f"(lo), "f"(hi));
    return r;
}
__device__ __forceinline__ void unpack2(unsigned long long v, float& lo, float& hi) {
    asm("mov.b64 {%0, %1}, %2;" : "=f"(lo), "=f"(hi) : "l"(v));
}
__device__ __forceinline__ void fma2(unsigned long long& d, unsigned long long a,
                                     unsigned long long b) {
    asm("fma.rn.f32x2 %0, %1, %2, %3;" : "=l"(d) : "l"(a), "l"(b), "l"(d));
}

__global__ void __launch_bounds__(NTHR, 1)
ea_kernel(const float* __restrict__ gL, const float* __restrict__ gR,
          const float* __restrict__ gK, const float* __restrict__ gBias,
          const float* __restrict__ gGamma, const float* __restrict__ gBeta,
          const float* __restrict__ gMean, const float* __restrict__ gVar,
          float* __restrict__ out)
{
    extern __shared__ float sm[];
    float* Qt = sm;                        // 128*165 (L ch 0..63, R ch 64..127)
    float* Kc = Qt + 128 * QROW;           // 128*52:  Kc[c][w*10+m]
    float* W4 = Kc + 128 * KROW;           // 8*160*11: per-group logit partials
    float* WS = W4 + 8 * 160 * 11;         // 160*12:  softmaxed weights

    const int t   = threadIdx.x;
    const int row = blockIdx.x;            // n*H + i
    const float* Lrow = gL + (size_t)row * (W_DIM * C_DIM);
    const float* Rrow = gR + (size_t)row * (W_DIM * C_DIM);

    // ---- zero the SAME-conv padding columns (128 ch x 5 pad cols = 640) ----
    {
        int c = t / 5, pc = t % 5;
        int col = (pc < 2) ? pc : (pc + 160);
        Qt[c * QROW + col] = 0.f;
    }

    // ---- load L,R rows (coalesced float4) -> transposed smem ----
    #pragma unroll
    for (int kk = 0; kk < 4; kk++) {
        int i4 = t + kk * NTHR;                    // 0..2559, = j*16 + cquad
        int j = i4 >> 4, c = (i4 & 15) << 2;
        float4 v = reinterpret_cast<const float4*>(Lrow)[i4];
        Qt[(c + 0) * QROW + 2 + j] = v.x;
        Qt[(c + 1) * QROW + 2 + j] = v.y;
        Qt[(c + 2) * QROW + 2 + j] = v.z;
        Qt[(c + 3) * QROW + 2 + j] = v.w;
        float4 u = reinterpret_cast<const float4*>(Rrow)[i4];
        Qt[(c + 64) * QROW + 2 + j] = u.x;
        Qt[(c + 65) * QROW + 2 + j] = u.y;
        Qt[(c + 66) * QROW + 2 + j] = u.z;
        Qt[(c + 67) * QROW + 2 + j] = u.w;
    }

    // ---- load conv kernel, HWIO (w,c,m) -> Kc[c][w*10+m] ----
    #pragma unroll
    for (int kk = 0; kk < 10; kk++) {
        int g = t + kk * NTHR;                     // 0..6399
        int m = g % 10;
        int c = (g / 10) & 127;
        int w = g / 1280;
        Kc[c * KROW + w * 10 + m] = gK[g];
    }
    __syncthreads();

    // ---- conv: thread = (j-pair, c-group of 16 channels) ----
    {
        const int jp = t % 80;                     // j = 2*jp, 2*jp+1
        const int cg = t / 80;                     // 0..7
        const int j0 = 2 * jp;

        unsigned long long accA[5], accB[5];       // m-pairs for j0 / j0+1
        #pragma unroll
        for (int p = 0; p < 5; p++) { accA[p] = 0ull; accB[p] = 0ull; }

        const float* qbase = Qt + (cg * 16) * QROW + j0;  // padded cols j0..j0+5
        const float* kbase = Kc + (cg * 16) * KROW;

        #pragma unroll 2
        for (int ci = 0; ci < 16; ci++) {
            const float* q = qbase + ci * QROW;
            float q0 = q[0], q1 = q[1], q2 = q[2], q3 = q[3], q4 = q[4], q5 = q[5];
            unsigned long long pk[6];
            pk[0] = pack2(q0, q0); pk[1] = pack2(q1, q1); pk[2] = pack2(q2, q2);
            pk[3] = pack2(q3, q3); pk[4] = pack2(q4, q4); pk[5] = pack2(q5, q5);

            const float* krow = kbase + ci * KROW;
            const ulonglong2* kp = reinterpret_cast<const ulonglong2*>(krow);
            #pragma unroll
            for (int i = 0; i < 12; i++) {
                ulonglong2 kv = kp[i];             // broadcast LDS.128
                const int pi0 = 2 * i, pi1 = 2 * i + 1;
                const int p0 = pi0 % 5, w0 = pi0 / 5;
                const int p1 = pi1 % 5, w1 = pi1 / 5;
                fma2(accA[p0], pk[w0],     kv.x);
                fma2(accB[p0], pk[w0 + 1], kv.x);
                fma2(accA[p1], pk[w1],     kv.y);
                fma2(accB[p1], pk[w1 + 1], kv.y);
            }
            unsigned long long kl =
                reinterpret_cast<const unsigned long long*>(krow)[24]; // w=4, m-pair 4
            fma2(accA[4], pk[4], kl);
            fma2(accB[4], pk[5], kl);
        }

        float* wdA = W4 + (cg * 160 + j0) * 11;    // odd stride => conflict-free
        float* wdB = wdA + 11;
        #pragma unroll
        for (int p = 0; p < 5; p++) {
            float lo, hi;
            unpack2(accA[p], lo, hi);
            wdA[2 * p] = lo; wdA[2 * p + 1] = hi;
            unpack2(accB[p], lo, hi);
            wdB[2 * p] = lo; wdB[2 * p + 1] = hi;
        }
    }
    __syncthreads();

    // ---- logit reduction (8 groups) + softmax + weight outputs ----
    if (t < 160) {
        float v[10];
        #pragma unroll
        for (int m = 0; m < 10; m++) {
            float a = gBias[m];
            #pragma unroll
            for (int g = 0; g < 8; g++)
                a += W4[(g * 160 + t) * 11 + m];
            v[m] = a;
        }
        float mx = v[0];
        #pragma unroll
        for (int m = 1; m < 10; m++) mx = fmaxf(mx, v[m]);
        float s = 0.f;
        #pragma unroll
        for (int m = 0; m < 10; m++) { float e = __expf(v[m] - mx); v[m] = e; s += e; }
        float inv = 1.f / s;
        float* wr = WS + t * 12;
        size_t wo = (size_t)row * 1600 + (size_t)t * 10;
        #pragma unroll
        for (int m = 0; m < 10; m++) {
            float wv = v[m] * inv;
            wr[m] = wv;
            out[W_OFF1 + wo + m] = wv;
            out[W_OFF2 + wo + m] = wv;
        }
    }
    __syncthreads();

    // ---- shiftmap gather + BN + tanh: thread = (k, group of 16 j) ----
    {
        const int k  = t & 63;
        const int g  = t >> 6;                     // 0..9
        const int j0 = g * 16;

        float sc = gGamma[k] / sqrtf(gVar[k] + 1e-3f);
        float sh = gBeta[k] - gMean[k] * sc;

        const float* Lc = Qt + k * QROW + 2;       // data columns
        const float* Rc = Qt + (64 + k) * QROW + 2;

        float lw[5], rw[5];
        #pragma unroll
        for (int s = 0; s < 5; s++) {
            int li = j0 - s; if (li < 0) li += 160;
            lw[s] = Lc[li];
            rw[s] = Rc[j0 + s];
        }

        float* xout = out + (size_t)(row * 160 + j0) * 64 + k;
        #pragma unroll
        for (int jj = 0; jj < 16; jj++) {
            int j = j0 + jj;
            const unsigned long long* wp =
                reinterpret_cast<const unsigned long long*>(WS + j * 12);
            unsigned long long a = 0ull;
            #pragma unroll
            for (int s = 0; s < 5; s++)
                fma2(a, wp[s], pack2(lw[s], rw[s]));
            float lo, hi;
            unpack2(a, lo, hi);
            float x = (lo + hi) * sc + sh;
            float e = __expf(2.f * x);             // tanh = 1 - 2/(e^{2x}+1)
            x = 1.f - 2.f / (e + 1.f);
            xout[(size_t)jj * 64] = x;

            int ln = j + 1; if (ln >= 160) ln -= 160;
            int rn = j + 5; if (rn >= 160) rn -= 160;
            lw[4] = lw[3]; lw[3] = lw[2]; lw[2] = lw[1]; lw[1] = lw[0];
            lw[0] = Lc[ln];
            rw[0] = rw[1]; rw[1] = rw[2]; rw[2] = rw[3]; rw[3] = rw[4];
            rw[4] = Rc[rn];
        }
    }
}

extern "C" void kernel_launch(void* const* d_in, const int* in_sizes, int n_in,
                              void* d_out, int out_size)
{
    const float* L     = (const float*)d_in[0];
    const float* R     = (const float*)d_in[1];
    const float* K     = (const float*)d_in[2];
    const float* bias  = (const float*)d_in[3];
    const float* gamma = (const float*)d_in[4];
    const float* beta  = (const float*)d_in[5];
    const float* mean  = (const float*)d_in[6];
    const float* var   = (const float*)d_in[7];
    float* out = (float*)d_out;

    const int smem = (128 * QROW + 128 * KROW + 8 * 160 * 11 + 160 * 12) * 4; // 175104 B
    cudaFuncSetAttribute(ea_kernel, cudaFuncAttributeMaxDynamicSharedMemorySize, smem);
    ea_kernel<<<512, NTHR, smem>>>(L, R, K, bias, gamma, beta, mean, var, out);
}